// round 13
// baseline (speedup 1.0000x reference)
#include <cuda_runtime.h>
#include <cuda_bf16.h>
#include <math.h>
#include <stdint.h>

#define N_NODES 50000
#define N_EDGES 800000
#define D 128
#define D4 (D / 4)
#define LN_EPS 1e-12f

#define MT 128                // nodes per MMA block
#define SWS 136               // smem row stride in bf16 (conflict-free)

// ---------------- scratch (no allocation allowed) ----------------
__device__ __align__(16) float g_h0[N_NODES * D];
__device__ __align__(16) float g_h1[N_NODES * D];
__device__ __align__(16) float g_agg[N_NODES * D];
__device__ __align__(16) __nv_bfloat16 g_Whi[4][D * D];  // Wl0,Wr0,Wl1,Wr1 hi
__device__ __align__(16) __nv_bfloat16 g_Wlo[4][D * D];  // lo residuals
__device__ int   g_deg[N_NODES];
__device__ int   g_row[N_NODES];
__device__ int   g_cursor[N_NODES];
__device__ float g_invd[N_NODES];
__device__ int   g_perm[N_EDGES];
__device__ int   g_total;

// ---------------- kernels ----------------

// Split 4 weight matrices into bf16 hi + lo residual (row-major [c][k]).
__global__ void w_split_kernel(const float* __restrict__ w0,
                               const float* __restrict__ w1,
                               const float* __restrict__ w2,
                               const float* __restrict__ w3,
                               __nv_bfloat16* __restrict__ whi,
                               __nv_bfloat16* __restrict__ wlo) {
    int i = blockIdx.x * blockDim.x + threadIdx.x;
    if (i >= 4 * D * D) return;
    int m = i >> 14;
    const float* w = (m == 0) ? w0 : (m == 1) ? w1 : (m == 2) ? w2 : w3;
    float f = w[i & 16383];
    __nv_bfloat16 hi = __float2bfloat16(f);
    __nv_bfloat16 lo = __float2bfloat16(f - __bfloat162float(hi));
    whi[i] = hi;
    wlo[i] = lo;
}

// Sum of 4 embedding lookups + LayerNorm. One block (128 threads) per node.
__global__ void embed_ln_kernel(const int* __restrict__ x,
                                const float* __restrict__ syn,
                                const float* __restrict__ lem,
                                const float* __restrict__ pos,
                                const float* __restrict__ sen,
                                const float* __restrict__ g,
                                const float* __restrict__ b,
                                float* __restrict__ out) {
    int node = blockIdx.x;
    int t = threadIdx.x;
    int4 xi = ((const int4*)x)[node];
    float f = syn[(long)xi.x * D + t] + pos[(long)xi.y * D + t] +
              sen[(long)xi.z * D + t] + lem[(long)xi.w * D + t];

    __shared__ float red1[4];
    __shared__ float red2[4];
    int w = t >> 5, l = t & 31;

    float s = f;
    #pragma unroll
    for (int o = 16; o > 0; o >>= 1) s += __shfl_xor_sync(0xffffffffu, s, o);
    if (l == 0) red1[w] = s;
    __syncthreads();
    float mu = (red1[0] + red1[1] + red1[2] + red1[3]) * (1.0f / D);

    float d = f - mu;
    float v = d * d;
    #pragma unroll
    for (int o = 16; o > 0; o >>= 1) v += __shfl_xor_sync(0xffffffffu, v, o);
    if (l == 0) red2[w] = v;
    __syncthreads();
    float var = (red2[0] + red2[1] + red2[2] + red2[3]) * (1.0f / D);

    out[node * D + t] = d * rsqrtf(var + LN_EPS) * g[t] + b[t];
}

// In-degree count, 4 edges per thread (int4).
__global__ void count_kernel(const int* __restrict__ ei, int* __restrict__ deg) {
    int e4 = blockIdx.x * blockDim.x + threadIdx.x;
    if (e4 >= N_EDGES / 4) return;
    int4 d = ((const int4*)(ei + N_EDGES))[e4];
    atomicAdd(&deg[d.x], 1);
    atomicAdd(&deg[d.y], 1);
    atomicAdd(&deg[d.z], 1);
    atomicAdd(&deg[d.w], 1);
}

// Segment-offset allocation: each node grabs a contiguous CSR segment.
__global__ void alloc_rows_kernel(const int* __restrict__ deg,
                                  int* __restrict__ row,
                                  int* __restrict__ cursor,
                                  float* __restrict__ invd,
                                  int* __restrict__ total) {
    int node = blockIdx.x * blockDim.x + threadIdx.x;
    if (node >= N_NODES) return;
    int d = deg[node];
    int start = atomicAdd(total, d);
    row[node] = start;
    cursor[node] = start;
    invd[node] = 1.0f / fmaxf((float)d, 1.0f);
}

// Fill permutation, 4 edges per thread (int4 loads).
__global__ void build_perm_kernel(const int* __restrict__ ei,
                                  int* __restrict__ cursor,
                                  int* __restrict__ perm) {
    int e4 = blockIdx.x * blockDim.x + threadIdx.x;
    if (e4 >= N_EDGES / 4) return;
    int4 s = ((const int4*)ei)[e4];
    int4 d = ((const int4*)(ei + N_EDGES))[e4];
    perm[atomicAdd(&cursor[d.x], 1)] = s.x;
    perm[atomicAdd(&cursor[d.y], 1)] = s.y;
    perm[atomicAdd(&cursor[d.z], 1)] = s.z;
    perm[atomicAdd(&cursor[d.w], 1)] = s.w;
}

// Mean-aggregate via CSR gather. TWO warps per node (even/odd 32-batches),
// combined through smem with a pair-scoped named barrier.
__global__ __launch_bounds__(256)
void gather_agg_kernel(const float* __restrict__ h,
                       const int* __restrict__ row,
                       const int* __restrict__ deg,
                       const int* __restrict__ perm,
                       const float* __restrict__ invd,
                       float* __restrict__ agg) {
    __shared__ float part[4][D];
    int wid = threadIdx.x >> 5;
    int lane = threadIdx.x & 31;
    int pairid = wid >> 1;       // 0..3
    int p = wid & 1;             // warp parity within pair
    int node = blockIdx.x * 4 + pairid;
    if (node >= N_NODES) return; // uniform across the pair
    int beg = row[node];
    int end = beg + deg[node];

    float4 acc = make_float4(0.f, 0.f, 0.f, 0.f);
    for (int j = beg + p * 32; j < end; j += 64) {
        int nj = min(32, end - j);
        int s = (j + lane < end) ? __ldg(&perm[j + lane]) : 0;
        int k = 0;
        for (; k + 8 <= nj; k += 8) {
            int s0 = __shfl_sync(0xffffffffu, s, k);
            int s1 = __shfl_sync(0xffffffffu, s, k + 1);
            int s2 = __shfl_sync(0xffffffffu, s, k + 2);
            int s3 = __shfl_sync(0xffffffffu, s, k + 3);
            int s4 = __shfl_sync(0xffffffffu, s, k + 4);
            int s5 = __shfl_sync(0xffffffffu, s, k + 5);
            int s6 = __shfl_sync(0xffffffffu, s, k + 6);
            int s7 = __shfl_sync(0xffffffffu, s, k + 7);
            float4 v0 = ((const float4*)h)[s0 * D4 + lane];
            float4 v1 = ((const float4*)h)[s1 * D4 + lane];
            float4 v2 = ((const float4*)h)[s2 * D4 + lane];
            float4 v3 = ((const float4*)h)[s3 * D4 + lane];
            float4 v4 = ((const float4*)h)[s4 * D4 + lane];
            float4 v5 = ((const float4*)h)[s5 * D4 + lane];
            float4 v6 = ((const float4*)h)[s6 * D4 + lane];
            float4 v7 = ((const float4*)h)[s7 * D4 + lane];
            acc.x += (v0.x + v1.x) + (v2.x + v3.x) + (v4.x + v5.x) + (v6.x + v7.x);
            acc.y += (v0.y + v1.y) + (v2.y + v3.y) + (v4.y + v5.y) + (v6.y + v7.y);
            acc.z += (v0.z + v1.z) + (v2.z + v3.z) + (v4.z + v5.z) + (v6.z + v7.z);
            acc.w += (v0.w + v1.w) + (v2.w + v3.w) + (v4.w + v5.w) + (v6.w + v7.w);
        }
        for (; k < nj; k++) {
            int sk = __shfl_sync(0xffffffffu, s, k);
            float4 v = ((const float4*)h)[sk * D4 + lane];
            acc.x += v.x; acc.y += v.y; acc.z += v.z; acc.w += v.w;
        }
    }

    if (p == 0) ((float4*)part[pairid])[lane] = acc;
    asm volatile("bar.sync %0, 64;" :: "r"(pairid + 1) : "memory");
    if (p == 1) {
        float4 o = ((const float4*)part[pairid])[lane];
        float iv = invd[node];
        o.x = (o.x + acc.x) * iv;
        o.y = (o.y + acc.y) * iv;
        o.z = (o.z + acc.z) * iv;
        o.w = (o.w + acc.w) * iv;
        ((float4*)agg)[node * D4 + lane] = o;
    }
}

// ---------------- tensor-core combine (warp mma.sync, bf16 hi/lo) ----------
__device__ __forceinline__ void mma_bf16(float c[4], uint32_t a0, uint32_t a1,
                                         uint32_t a2, uint32_t a3,
                                         uint32_t b0, uint32_t b1) {
    asm volatile(
        "mma.sync.aligned.m16n8k16.row.col.f32.bf16.bf16.f32 "
        "{%0,%1,%2,%3}, {%4,%5,%6,%7}, {%8,%9}, {%0,%1,%2,%3};"
        : "+f"(c[0]), "+f"(c[1]), "+f"(c[2]), "+f"(c[3])
        : "r"(a0), "r"(a1), "r"(a2), "r"(a3), "r"(b0), "r"(b1));
}

// out[n][c] = act( agg[n].Wl[c] + bl[c] + h[n].Wr[c] )
// Block: 128 nodes x 128 cols, 256 threads (8 warps, each 32x64 tile).
__global__ __launch_bounds__(256)
void mma_combine_kernel(const float* __restrict__ agg,
                        const float* __restrict__ h,
                        const __nv_bfloat16* __restrict__ WhiL,
                        const __nv_bfloat16* __restrict__ WloL,
                        const __nv_bfloat16* __restrict__ WhiR,
                        const __nv_bfloat16* __restrict__ WloR,
                        const float* __restrict__ bl,
                        float* __restrict__ out,
                        int relu) {
    extern __shared__ __align__(16) char smem[];
    __nv_bfloat16* sWhi = (__nv_bfloat16*)smem;                    // [128][SWS]
    __nv_bfloat16* sWlo = sWhi + D * SWS;
    __nv_bfloat16* sAhi = sWlo + D * SWS;                          // [128][SWS]
    __nv_bfloat16* sAlo = sAhi + MT * SWS;
    float* sbias = (float*)(sAlo + MT * SWS);                      // [128]

    int tid = threadIdx.x;
    int wid = tid >> 5, lane = tid & 31;
    int g = lane >> 2, tig = lane & 3;
    int n0 = blockIdx.x * MT;
    int r0 = (wid & 3) * 32;          // warp row base within tile (0..96)
    int cb = (wid >> 2) * 64;         // warp col base (0 or 64)

    if (tid < 128) sbias[tid] = bl[tid];

    float C[2][8][4];
    #pragma unroll
    for (int m = 0; m < 2; m++)
        #pragma unroll
        for (int nt = 0; nt < 8; nt++)
            #pragma unroll
            for (int q = 0; q < 4; q++) C[m][nt][q] = 0.f;

    for (int pass = 0; pass < 2; pass++) {
        const float* asrc = pass ? h : agg;
        const __nv_bfloat16* whi = pass ? WhiR : WhiL;
        const __nv_bfloat16* wlo = pass ? WloR : WloL;
        __syncthreads();   // previous pass's smem fully consumed

        for (int i = tid; i < D * 16; i += 256) {
            int r = i >> 4, c16 = i & 15;
            *(uint4*)&sWhi[r * SWS + c16 * 8] = ((const uint4*)whi)[r * 16 + c16];
            *(uint4*)&sWlo[r * SWS + c16 * 8] = ((const uint4*)wlo)[r * 16 + c16];
        }
        for (int i = tid; i < MT * 32; i += 256) {
            int r = i >> 5, c4 = i & 31;
            int node = n0 + r;
            float4 v = make_float4(0.f, 0.f, 0.f, 0.f);
            if (node < N_NODES) v = ((const float4*)asrc)[node * 32 + c4];
            __nv_bfloat162 h01 = __floats2bfloat162_rn(v.x, v.y);
            __nv_bfloat162 h23 = __floats2bfloat162_rn(v.z, v.w);
            float2 f01 = __bfloat1622float2(h01);
            float2 f23 = __bfloat1622float2(h23);
            __nv_bfloat162 l01 = __floats2bfloat162_rn(v.x - f01.x, v.y - f01.y);
            __nv_bfloat162 l23 = __floats2bfloat162_rn(v.z - f23.x, v.w - f23.y);
            uint2 uh, ul;
            uh.x = *(unsigned*)&h01; uh.y = *(unsigned*)&h23;
            ul.x = *(unsigned*)&l01; ul.y = *(unsigned*)&l23;
            *(uint2*)&sAhi[r * SWS + c4 * 4] = uh;
            *(uint2*)&sAlo[r * SWS + c4 * 4] = ul;
        }
        __syncthreads();

        #pragma unroll
        for (int ks = 0; ks < 8; ks++) {
            int kc = ks * 16 + tig * 2;
            uint32_t ah[2][4], al[2][4];
            #pragma unroll
            for (int m = 0; m < 2; m++) {
                int arow = r0 + m * 16 + g;
                ah[m][0] = *(uint32_t*)&sAhi[arow * SWS + kc];
                ah[m][1] = *(uint32_t*)&sAhi[(arow + 8) * SWS + kc];
                ah[m][2] = *(uint32_t*)&sAhi[arow * SWS + kc + 8];
                ah[m][3] = *(uint32_t*)&sAhi[(arow + 8) * SWS + kc + 8];
                al[m][0] = *(uint32_t*)&sAlo[arow * SWS + kc];
                al[m][1] = *(uint32_t*)&sAlo[(arow + 8) * SWS + kc];
                al[m][2] = *(uint32_t*)&sAlo[arow * SWS + kc + 8];
                al[m][3] = *(uint32_t*)&sAlo[(arow + 8) * SWS + kc + 8];
            }
            #pragma unroll
            for (int nt = 0; nt < 8; nt++) {
                int nrow = cb + nt * 8 + g;
                uint32_t bh0 = *(uint32_t*)&sWhi[nrow * SWS + kc];
                uint32_t bh1 = *(uint32_t*)&sWhi[nrow * SWS + kc + 8];
                uint32_t bl0 = *(uint32_t*)&sWlo[nrow * SWS + kc];
                uint32_t bl1 = *(uint32_t*)&sWlo[nrow * SWS + kc + 8];
                #pragma unroll
                for (int m = 0; m < 2; m++) {
                    mma_bf16(C[m][nt], ah[m][0], ah[m][1], ah[m][2], ah[m][3], bh0, bh1);
                    mma_bf16(C[m][nt], ah[m][0], ah[m][1], ah[m][2], ah[m][3], bl0, bl1);
                    mma_bf16(C[m][nt], al[m][0], al[m][1], al[m][2], al[m][3], bh0, bh1);
                }
            }
        }
    }

    #pragma unroll
    for (int m = 0; m < 2; m++) {
        int row0 = n0 + r0 + m * 16 + g;
        int row1 = row0 + 8;
        #pragma unroll
        for (int nt = 0; nt < 8; nt++) {
            int col = cb + nt * 8 + tig * 2;
            float b0 = sbias[col], b1 = sbias[col + 1];
            float2 o0, o1;
            o0.x = C[m][nt][0] + b0; o0.y = C[m][nt][1] + b1;
            o1.x = C[m][nt][2] + b0; o1.y = C[m][nt][3] + b1;
            if (relu) {
                o0.x = fmaxf(o0.x, 0.f); o0.y = fmaxf(o0.y, 0.f);
                o1.x = fmaxf(o1.x, 0.f); o1.y = fmaxf(o1.y, 0.f);
            }
            if (row0 < N_NODES) *(float2*)&out[row0 * D + col] = o0;
            if (row1 < N_NODES) *(float2*)&out[row1 * D + col] = o1;
        }
    }
}

// ---------------- launch ----------------

extern "C" void kernel_launch(void* const* d_in, const int* in_sizes, int n_in,
                              void* d_out, int out_size) {
    const int*   x    = (const int*)d_in[0];
    const int*   ei   = (const int*)d_in[1];
    const float* syn  = (const float*)d_in[2];
    const float* lem  = (const float*)d_in[3];
    const float* pos  = (const float*)d_in[4];
    const float* sen  = (const float*)d_in[5];
    const float* ln_g = (const float*)d_in[6];
    const float* ln_b = (const float*)d_in[7];
    const float* Wl0  = (const float*)d_in[8];
    const float* bl0  = (const float*)d_in[9];
    const float* Wr0  = (const float*)d_in[10];
    const float* Wl1  = (const float*)d_in[11];
    const float* bl1  = (const float*)d_in[12];
    const float* Wr1  = (const float*)d_in[13];
    float* out = (float*)d_out;

    float *h0, *h1, *agg, *invd;
    __nv_bfloat16 *whi, *wlo;
    int *deg, *row, *cursor, *perm, *total;
    cudaGetSymbolAddress((void**)&h0,     g_h0);
    cudaGetSymbolAddress((void**)&h1,     g_h1);
    cudaGetSymbolAddress((void**)&agg,    g_agg);
    cudaGetSymbolAddress((void**)&whi,    g_Whi);
    cudaGetSymbolAddress((void**)&wlo,    g_Wlo);
    cudaGetSymbolAddress((void**)&deg,    g_deg);
    cudaGetSymbolAddress((void**)&row,    g_row);
    cudaGetSymbolAddress((void**)&cursor, g_cursor);
    cudaGetSymbolAddress((void**)&invd,   g_invd);
    cudaGetSymbolAddress((void**)&perm,   g_perm);
    cudaGetSymbolAddress((void**)&total,  g_total);

    const int smem_bytes = 4 * D * SWS * 2 + D * 4;
    cudaFuncSetAttribute(mma_combine_kernel,
                         cudaFuncAttributeMaxDynamicSharedMemorySize, smem_bytes);

    const int e4blocks = (N_EDGES / 4 + 255) / 256;
    const int gather_blocks = (N_NODES + 3) / 4;
    const int mma_blocks = (N_NODES + MT - 1) / MT;   // 391

    cudaMemsetAsync(deg, 0, N_NODES * sizeof(int));
    cudaMemsetAsync(total, 0, sizeof(int));

    // 0. weight hi/lo split (order: Wl0, Wr0, Wl1, Wr1)
    w_split_kernel<<<(4 * D * D + 255) / 256, 256>>>(Wl0, Wr0, Wl1, Wr1, whi, wlo);

    // 1. embeddings + LayerNorm -> h0
    embed_ln_kernel<<<N_NODES, 128>>>(x, syn, lem, pos, sen, ln_g, ln_b, h0);

    // 2. CSR build (scan-free segment allocation)
    count_kernel<<<e4blocks, 256>>>(ei, deg);
    alloc_rows_kernel<<<(N_NODES + 255) / 256, 256>>>(deg, row, cursor, invd, total);
    build_perm_kernel<<<e4blocks, 256>>>(ei, cursor, perm);

    // 3. layer 0
    gather_agg_kernel<<<gather_blocks, 256>>>(h0, row, deg, perm, invd, agg);
    mma_combine_kernel<<<mma_blocks, 256, smem_bytes>>>(agg, h0,
        whi + 0 * D * D, wlo + 0 * D * D, whi + 1 * D * D, wlo + 1 * D * D,
        bl0, h1, 1);

    // 4. layer 1
    gather_agg_kernel<<<gather_blocks, 256>>>(h1, row, deg, perm, invd, agg);
    mma_combine_kernel<<<mma_blocks, 256, smem_bytes>>>(agg, h1,
        whi + 2 * D * D, wlo + 2 * D * D, whi + 3 * D * D, wlo + 3 * D * D,
        bl1, out, 0);
}

// round 14
// speedup vs baseline: 1.3257x; 1.3257x over previous
#include <cuda_runtime.h>
#include <cuda_bf16.h>
#include <math.h>
#include <stdint.h>

#define N_NODES 50000
#define N_EDGES 800000
#define D 128
#define D4 (D / 4)
#define LN_EPS 1e-12f

#define MT 128                // nodes per MMA block
#define SWS 136               // smem row stride in bf16 (conflict-free)

// ---------------- scratch (no allocation allowed) ----------------
__device__ __align__(16) float g_h0[N_NODES * D];
__device__ __align__(16) float g_h1[N_NODES * D];
__device__ __align__(16) float g_agg[N_NODES * D];
__device__ __align__(16) __nv_bfloat16 g_Whi[4][D * D];  // Wl0,Wr0,Wl1,Wr1 hi
__device__ __align__(16) __nv_bfloat16 g_Wlo[4][D * D];  // lo residuals
__device__ int   g_deg[N_NODES + 1];   // [N_NODES] = total cursor
__device__ int   g_row[N_NODES];
__device__ int   g_cursor[N_NODES];
__device__ float g_invd[N_NODES];
__device__ int   g_perm[N_EDGES];

// ---------------- kernels ----------------

// Split 4 weight matrices into bf16 hi + lo residual (row-major [c][k]).
__global__ void w_split_kernel(const float* __restrict__ w0,
                               const float* __restrict__ w1,
                               const float* __restrict__ w2,
                               const float* __restrict__ w3,
                               __nv_bfloat16* __restrict__ whi,
                               __nv_bfloat16* __restrict__ wlo) {
    int i = blockIdx.x * blockDim.x + threadIdx.x;
    if (i >= 4 * D * D) return;
    int m = i >> 14;
    const float* w = (m == 0) ? w0 : (m == 1) ? w1 : (m == 2) ? w2 : w3;
    float f = w[i & 16383];
    __nv_bfloat16 hi = __float2bfloat16(f);
    __nv_bfloat16 lo = __float2bfloat16(f - __bfloat162float(hi));
    whi[i] = hi;
    wlo[i] = lo;
}

// Sum of 4 embedding lookups + LayerNorm. One block (128 threads) per node.
__global__ void embed_ln_kernel(const int* __restrict__ x,
                                const float* __restrict__ syn,
                                const float* __restrict__ lem,
                                const float* __restrict__ pos,
                                const float* __restrict__ sen,
                                const float* __restrict__ g,
                                const float* __restrict__ b,
                                float* __restrict__ out) {
    int node = blockIdx.x;
    int t = threadIdx.x;
    int4 xi = ((const int4*)x)[node];
    float f = syn[(long)xi.x * D + t] + pos[(long)xi.y * D + t] +
              sen[(long)xi.z * D + t] + lem[(long)xi.w * D + t];

    __shared__ float red1[4];
    __shared__ float red2[4];
    int w = t >> 5, l = t & 31;

    float s = f;
    #pragma unroll
    for (int o = 16; o > 0; o >>= 1) s += __shfl_xor_sync(0xffffffffu, s, o);
    if (l == 0) red1[w] = s;
    __syncthreads();
    float mu = (red1[0] + red1[1] + red1[2] + red1[3]) * (1.0f / D);

    float d = f - mu;
    float v = d * d;
    #pragma unroll
    for (int o = 16; o > 0; o >>= 1) v += __shfl_xor_sync(0xffffffffu, v, o);
    if (l == 0) red2[w] = v;
    __syncthreads();
    float var = (red2[0] + red2[1] + red2[2] + red2[3]) * (1.0f / D);

    out[node * D + t] = d * rsqrtf(var + LN_EPS) * g[t] + b[t];
}

// In-degree count (scalar, one edge per thread).
__global__ void count_kernel(const int* __restrict__ ei, int* __restrict__ deg) {
    int e = blockIdx.x * blockDim.x + threadIdx.x;
    if (e < N_EDGES) atomicAdd(&deg[ei[N_EDGES + e]], 1);
}

// Segment-offset allocation: each node grabs a contiguous CSR segment.
// total cursor lives at deg[N_NODES].
__global__ void alloc_rows_kernel(int* __restrict__ deg,
                                  int* __restrict__ row,
                                  int* __restrict__ cursor,
                                  float* __restrict__ invd) {
    int node = blockIdx.x * blockDim.x + threadIdx.x;
    if (node >= N_NODES) return;
    int d = deg[node];
    int start = atomicAdd(&deg[N_NODES], d);
    row[node] = start;
    cursor[node] = start;
    invd[node] = 1.0f / fmaxf((float)d, 1.0f);
}

// Fill permutation (scalar).
__global__ void build_perm_kernel(const int* __restrict__ ei,
                                  int* __restrict__ cursor,
                                  int* __restrict__ perm) {
    int e = blockIdx.x * blockDim.x + threadIdx.x;
    if (e >= N_EDGES) return;
    int dst = ei[N_EDGES + e];
    int pos = atomicAdd(&cursor[dst], 1);
    perm[pos] = ei[e];
}

// Mean-aggregate via CSR gather. One warp per node; lane = float4 chunk.
__global__ __launch_bounds__(256)
void gather_agg_kernel(const float* __restrict__ h,
                       const int* __restrict__ row,
                       const int* __restrict__ deg,
                       const int* __restrict__ perm,
                       const float* __restrict__ invd,
                       float* __restrict__ agg) {
    int node = blockIdx.x * 8 + (threadIdx.x >> 5);
    int lane = threadIdx.x & 31;
    if (node >= N_NODES) return;
    int beg = row[node];
    int end = beg + deg[node];

    float4 acc = make_float4(0.f, 0.f, 0.f, 0.f);
    for (int j = beg; j < end; j += 32) {
        int nj = min(32, end - j);
        int s = (j + lane < end) ? __ldg(&perm[j + lane]) : 0;
        int k = 0;
        for (; k + 8 <= nj; k += 8) {
            int s0 = __shfl_sync(0xffffffffu, s, k);
            int s1 = __shfl_sync(0xffffffffu, s, k + 1);
            int s2 = __shfl_sync(0xffffffffu, s, k + 2);
            int s3 = __shfl_sync(0xffffffffu, s, k + 3);
            int s4 = __shfl_sync(0xffffffffu, s, k + 4);
            int s5 = __shfl_sync(0xffffffffu, s, k + 5);
            int s6 = __shfl_sync(0xffffffffu, s, k + 6);
            int s7 = __shfl_sync(0xffffffffu, s, k + 7);
            float4 v0 = ((const float4*)h)[s0 * D4 + lane];
            float4 v1 = ((const float4*)h)[s1 * D4 + lane];
            float4 v2 = ((const float4*)h)[s2 * D4 + lane];
            float4 v3 = ((const float4*)h)[s3 * D4 + lane];
            float4 v4 = ((const float4*)h)[s4 * D4 + lane];
            float4 v5 = ((const float4*)h)[s5 * D4 + lane];
            float4 v6 = ((const float4*)h)[s6 * D4 + lane];
            float4 v7 = ((const float4*)h)[s7 * D4 + lane];
            acc.x += (v0.x + v1.x) + (v2.x + v3.x) + (v4.x + v5.x) + (v6.x + v7.x);
            acc.y += (v0.y + v1.y) + (v2.y + v3.y) + (v4.y + v5.y) + (v6.y + v7.y);
            acc.z += (v0.z + v1.z) + (v2.z + v3.z) + (v4.z + v5.z) + (v6.z + v7.z);
            acc.w += (v0.w + v1.w) + (v2.w + v3.w) + (v4.w + v5.w) + (v6.w + v7.w);
        }
        for (; k < nj; k++) {
            int sk = __shfl_sync(0xffffffffu, s, k);
            float4 v = ((const float4*)h)[sk * D4 + lane];
            acc.x += v.x; acc.y += v.y; acc.z += v.z; acc.w += v.w;
        }
    }
    float iv = invd[node];
    acc.x *= iv; acc.y *= iv; acc.z *= iv; acc.w *= iv;
    ((float4*)agg)[node * D4 + lane] = acc;
}

// ---------------- tensor-core combine (warp mma.sync, bf16 hi/lo) ----------
__device__ __forceinline__ void mma_bf16(float c[4], uint32_t a0, uint32_t a1,
                                         uint32_t a2, uint32_t a3,
                                         uint32_t b0, uint32_t b1) {
    asm volatile(
        "mma.sync.aligned.m16n8k16.row.col.f32.bf16.bf16.f32 "
        "{%0,%1,%2,%3}, {%4,%5,%6,%7}, {%8,%9}, {%0,%1,%2,%3};"
        : "+f"(c[0]), "+f"(c[1]), "+f"(c[2]), "+f"(c[3])
        : "r"(a0), "r"(a1), "r"(a2), "r"(a3), "r"(b0), "r"(b1));
}

// out[n][c] = act( agg[n].Wl[c] + bl[c] + h[n].Wr[c] )
// Block: 128 nodes x 128 cols, 256 threads (8 warps, each 32x64 tile).
__global__ __launch_bounds__(256)
void mma_combine_kernel(const float* __restrict__ agg,
                        const float* __restrict__ h,
                        const __nv_bfloat16* __restrict__ WhiL,
                        const __nv_bfloat16* __restrict__ WloL,
                        const __nv_bfloat16* __restrict__ WhiR,
                        const __nv_bfloat16* __restrict__ WloR,
                        const float* __restrict__ bl,
                        float* __restrict__ out,
                        int relu) {
    extern __shared__ __align__(16) char smem[];
    __nv_bfloat16* sWhi = (__nv_bfloat16*)smem;                    // [128][SWS]
    __nv_bfloat16* sWlo = sWhi + D * SWS;
    __nv_bfloat16* sAhi = sWlo + D * SWS;                          // [128][SWS]
    __nv_bfloat16* sAlo = sAhi + MT * SWS;
    float* sbias = (float*)(sAlo + MT * SWS);                      // [128]

    int tid = threadIdx.x;
    int wid = tid >> 5, lane = tid & 31;
    int g = lane >> 2, tig = lane & 3;
    int n0 = blockIdx.x * MT;
    int r0 = (wid & 3) * 32;          // warp row base within tile (0..96)
    int cb = (wid >> 2) * 64;         // warp col base (0 or 64)

    if (tid < 128) sbias[tid] = bl[tid];

    float C[2][8][4];
    #pragma unroll
    for (int m = 0; m < 2; m++)
        #pragma unroll
        for (int nt = 0; nt < 8; nt++)
            #pragma unroll
            for (int q = 0; q < 4; q++) C[m][nt][q] = 0.f;

    for (int pass = 0; pass < 2; pass++) {
        const float* asrc = pass ? h : agg;
        const __nv_bfloat16* whi = pass ? WhiR : WhiL;
        const __nv_bfloat16* wlo = pass ? WloR : WloL;
        __syncthreads();   // previous pass's smem fully consumed

        for (int i = tid; i < D * 16; i += 256) {
            int r = i >> 4, c16 = i & 15;
            *(uint4*)&sWhi[r * SWS + c16 * 8] = ((const uint4*)whi)[r * 16 + c16];
            *(uint4*)&sWlo[r * SWS + c16 * 8] = ((const uint4*)wlo)[r * 16 + c16];
        }
        for (int i = tid; i < MT * 32; i += 256) {
            int r = i >> 5, c4 = i & 31;
            int node = n0 + r;
            float4 v = make_float4(0.f, 0.f, 0.f, 0.f);
            if (node < N_NODES) v = ((const float4*)asrc)[node * 32 + c4];
            __nv_bfloat162 h01 = __floats2bfloat162_rn(v.x, v.y);
            __nv_bfloat162 h23 = __floats2bfloat162_rn(v.z, v.w);
            float2 f01 = __bfloat1622float2(h01);
            float2 f23 = __bfloat1622float2(h23);
            __nv_bfloat162 l01 = __floats2bfloat162_rn(v.x - f01.x, v.y - f01.y);
            __nv_bfloat162 l23 = __floats2bfloat162_rn(v.z - f23.x, v.w - f23.y);
            uint2 uh, ul;
            uh.x = *(unsigned*)&h01; uh.y = *(unsigned*)&h23;
            ul.x = *(unsigned*)&l01; ul.y = *(unsigned*)&l23;
            *(uint2*)&sAhi[r * SWS + c4 * 4] = uh;
            *(uint2*)&sAlo[r * SWS + c4 * 4] = ul;
        }
        __syncthreads();

        #pragma unroll
        for (int ks = 0; ks < 8; ks++) {
            int kc = ks * 16 + tig * 2;
            uint32_t ah[2][4], al[2][4];
            #pragma unroll
            for (int m = 0; m < 2; m++) {
                int arow = r0 + m * 16 + g;
                ah[m][0] = *(uint32_t*)&sAhi[arow * SWS + kc];
                ah[m][1] = *(uint32_t*)&sAhi[(arow + 8) * SWS + kc];
                ah[m][2] = *(uint32_t*)&sAhi[arow * SWS + kc + 8];
                ah[m][3] = *(uint32_t*)&sAhi[(arow + 8) * SWS + kc + 8];
                al[m][0] = *(uint32_t*)&sAlo[arow * SWS + kc];
                al[m][1] = *(uint32_t*)&sAlo[(arow + 8) * SWS + kc];
                al[m][2] = *(uint32_t*)&sAlo[arow * SWS + kc + 8];
                al[m][3] = *(uint32_t*)&sAlo[(arow + 8) * SWS + kc + 8];
            }
            #pragma unroll
            for (int nt = 0; nt < 8; nt++) {
                int nrow = cb + nt * 8 + g;
                uint32_t bh0 = *(uint32_t*)&sWhi[nrow * SWS + kc];
                uint32_t bh1 = *(uint32_t*)&sWhi[nrow * SWS + kc + 8];
                uint32_t bl0 = *(uint32_t*)&sWlo[nrow * SWS + kc];
                uint32_t bl1 = *(uint32_t*)&sWlo[nrow * SWS + kc + 8];
                #pragma unroll
                for (int m = 0; m < 2; m++) {
                    mma_bf16(C[m][nt], ah[m][0], ah[m][1], ah[m][2], ah[m][3], bh0, bh1);
                    mma_bf16(C[m][nt], ah[m][0], ah[m][1], ah[m][2], ah[m][3], bl0, bl1);
                    mma_bf16(C[m][nt], al[m][0], al[m][1], al[m][2], al[m][3], bh0, bh1);
                }
            }
        }
    }

    #pragma unroll
    for (int m = 0; m < 2; m++) {
        int row0 = n0 + r0 + m * 16 + g;
        int row1 = row0 + 8;
        #pragma unroll
        for (int nt = 0; nt < 8; nt++) {
            int col = cb + nt * 8 + tig * 2;
            float b0 = sbias[col], b1 = sbias[col + 1];
            float2 o0, o1;
            o0.x = C[m][nt][0] + b0; o0.y = C[m][nt][1] + b1;
            o1.x = C[m][nt][2] + b0; o1.y = C[m][nt][3] + b1;
            if (relu) {
                o0.x = fmaxf(o0.x, 0.f); o0.y = fmaxf(o0.y, 0.f);
                o1.x = fmaxf(o1.x, 0.f); o1.y = fmaxf(o1.y, 0.f);
            }
            if (row0 < N_NODES) *(float2*)&out[row0 * D + col] = o0;
            if (row1 < N_NODES) *(float2*)&out[row1 * D + col] = o1;
        }
    }
}

// ---------------- launch ----------------

extern "C" void kernel_launch(void* const* d_in, const int* in_sizes, int n_in,
                              void* d_out, int out_size) {
    const int*   x    = (const int*)d_in[0];
    const int*   ei   = (const int*)d_in[1];
    const float* syn  = (const float*)d_in[2];
    const float* lem  = (const float*)d_in[3];
    const float* pos  = (const float*)d_in[4];
    const float* sen  = (const float*)d_in[5];
    const float* ln_g = (const float*)d_in[6];
    const float* ln_b = (const float*)d_in[7];
    const float* Wl0  = (const float*)d_in[8];
    const float* bl0  = (const float*)d_in[9];
    const float* Wr0  = (const float*)d_in[10];
    const float* Wl1  = (const float*)d_in[11];
    const float* bl1  = (const float*)d_in[12];
    const float* Wr1  = (const float*)d_in[13];
    float* out = (float*)d_out;

    float *h0, *h1, *agg, *invd;
    __nv_bfloat16 *whi, *wlo;
    int *deg, *row, *cursor, *perm;
    cudaGetSymbolAddress((void**)&h0,     g_h0);
    cudaGetSymbolAddress((void**)&h1,     g_h1);
    cudaGetSymbolAddress((void**)&agg,    g_agg);
    cudaGetSymbolAddress((void**)&whi,    g_Whi);
    cudaGetSymbolAddress((void**)&wlo,    g_Wlo);
    cudaGetSymbolAddress((void**)&deg,    g_deg);
    cudaGetSymbolAddress((void**)&row,    g_row);
    cudaGetSymbolAddress((void**)&cursor, g_cursor);
    cudaGetSymbolAddress((void**)&invd,   g_invd);
    cudaGetSymbolAddress((void**)&perm,   g_perm);

    const int smem_bytes = 4 * D * SWS * 2 + D * 4;
    cudaFuncSetAttribute(mma_combine_kernel,
                         cudaFuncAttributeMaxDynamicSharedMemorySize, smem_bytes);

    const int eblocks = (N_EDGES + 255) / 256;
    const int gather_blocks = (N_NODES + 7) / 8;
    const int mma_blocks = (N_NODES + MT - 1) / MT;   // 391

    // single memset: deg[0..N_NODES-1] + total cursor at deg[N_NODES]
    cudaMemsetAsync(deg, 0, (N_NODES + 1) * sizeof(int));

    // launches 2-5: embed, count, alloc, perm  -> gather0 is launch #6 (ncu -s 5)
    embed_ln_kernel<<<N_NODES, 128>>>(x, syn, lem, pos, sen, ln_g, ln_b, h0);
    count_kernel<<<eblocks, 256>>>(ei, deg);
    alloc_rows_kernel<<<(N_NODES + 255) / 256, 256>>>(deg, row, cursor, invd);
    build_perm_kernel<<<eblocks, 256>>>(ei, cursor, perm);

    // layer 0
    gather_agg_kernel<<<gather_blocks, 256>>>(h0, row, deg, perm, invd, agg);
    w_split_kernel<<<(4 * D * D + 255) / 256, 256>>>(Wl0, Wr0, Wl1, Wr1, whi, wlo);
    mma_combine_kernel<<<mma_blocks, 256, smem_bytes>>>(agg, h0,
        whi + 0 * D * D, wlo + 0 * D * D, whi + 1 * D * D, wlo + 1 * D * D,
        bl0, h1, 1);

    // layer 1
    gather_agg_kernel<<<gather_blocks, 256>>>(h1, row, deg, perm, invd, agg);
    mma_combine_kernel<<<mma_blocks, 256, smem_bytes>>>(agg, h1,
        whi + 2 * D * D, wlo + 2 * D * D, whi + 3 * D * D, wlo + 3 * D * D,
        bl1, out, 0);
}

// round 15
// speedup vs baseline: 1.3768x; 1.0386x over previous
#include <cuda_runtime.h>
#include <cuda_bf16.h>
#include <math.h>
#include <stdint.h>

#define N_NODES 50000
#define N_EDGES 800000
#define D 128
#define D4 (D / 4)
#define LN_EPS 1e-12f

#define MT 128                // nodes per MMA block
#define SWS 136               // smem row stride in bf16 (conflict-free)

// ---------------- scratch (no allocation allowed) ----------------
__device__ __align__(16) float g_h0[N_NODES * D];
__device__ __align__(16) float g_h1[N_NODES * D];
__device__ __align__(16) float g_agg[N_NODES * D];
__device__ __align__(16) __nv_bfloat16 g_Whi[4][D * D];  // Wl0,Wr0,Wl1,Wr1 hi
__device__ __align__(16) __nv_bfloat16 g_Wlo[4][D * D];  // lo residuals
__device__ int   g_deg[N_NODES + 1];   // [N_NODES] = total cursor
__device__ int   g_row[N_NODES];
__device__ int   g_cursor[N_NODES];
__device__ float g_invd[N_NODES];
__device__ int   g_perm[N_EDGES];

// ---------------- kernels ----------------

// Fused: embeddings + LayerNorm (one block per node) AND in-degree count
// (first N_EDGES global threads each count one edge).
__global__ void embed_count_kernel(const int* __restrict__ x,
                                   const float* __restrict__ syn,
                                   const float* __restrict__ lem,
                                   const float* __restrict__ pos,
                                   const float* __restrict__ sen,
                                   const float* __restrict__ g,
                                   const float* __restrict__ b,
                                   const int* __restrict__ ei,
                                   int* __restrict__ deg,
                                   float* __restrict__ out) {
    int node = blockIdx.x;
    int t = threadIdx.x;

    // edge-count side job (independent of embed work)
    int gtid = node * 128 + t;
    if (gtid < N_EDGES) atomicAdd(&deg[ei[N_EDGES + gtid]], 1);

    int4 xi = ((const int4*)x)[node];
    float f = syn[(long)xi.x * D + t] + pos[(long)xi.y * D + t] +
              sen[(long)xi.z * D + t] + lem[(long)xi.w * D + t];

    __shared__ float red1[4];
    __shared__ float red2[4];
    int w = t >> 5, l = t & 31;

    float s = f;
    #pragma unroll
    for (int o = 16; o > 0; o >>= 1) s += __shfl_xor_sync(0xffffffffu, s, o);
    if (l == 0) red1[w] = s;
    __syncthreads();
    float mu = (red1[0] + red1[1] + red1[2] + red1[3]) * (1.0f / D);

    float d = f - mu;
    float v = d * d;
    #pragma unroll
    for (int o = 16; o > 0; o >>= 1) v += __shfl_xor_sync(0xffffffffu, v, o);
    if (l == 0) red2[w] = v;
    __syncthreads();
    float var = (red2[0] + red2[1] + red2[2] + red2[3]) * (1.0f / D);

    out[node * D + t] = d * rsqrtf(var + LN_EPS) * g[t] + b[t];
}

// Fused: segment-offset CSR allocation (threads < N_NODES) AND weight hi/lo
// split (all 65536 threads, one element each). Grid must be 256x256.
__global__ __launch_bounds__(256)
void alloc_wsplit_kernel(int* __restrict__ deg,
                         int* __restrict__ row,
                         int* __restrict__ cursor,
                         float* __restrict__ invd,
                         const float* __restrict__ w0,
                         const float* __restrict__ w1,
                         const float* __restrict__ w2,
                         const float* __restrict__ w3,
                         __nv_bfloat16* __restrict__ whi,
                         __nv_bfloat16* __restrict__ wlo) {
    int i = blockIdx.x * 256 + threadIdx.x;   // 0 .. 65535 = 4*D*D

    // weight split side job
    int m = i >> 14;
    const float* w = (m == 0) ? w0 : (m == 1) ? w1 : (m == 2) ? w2 : w3;
    float f = w[i & 16383];
    __nv_bfloat16 hi = __float2bfloat16(f);
    __nv_bfloat16 lo = __float2bfloat16(f - __bfloat162float(hi));
    whi[i] = hi;
    wlo[i] = lo;

    // CSR segment allocation
    if (i < N_NODES) {
        int d = deg[i];
        int start = atomicAdd(&deg[N_NODES], d);
        row[i] = start;
        cursor[i] = start;
        invd[i] = 1.0f / fmaxf((float)d, 1.0f);
    }
}

// Fill permutation (scalar).
__global__ void build_perm_kernel(const int* __restrict__ ei,
                                  int* __restrict__ cursor,
                                  int* __restrict__ perm) {
    int e = blockIdx.x * blockDim.x + threadIdx.x;
    if (e >= N_EDGES) return;
    int dst = ei[N_EDGES + e];
    int pos = atomicAdd(&cursor[dst], 1);
    perm[pos] = ei[e];
}

// Mean-aggregate via CSR gather. One warp per node; lane = float4 chunk.
__global__ __launch_bounds__(256)
void gather_agg_kernel(const float* __restrict__ h,
                       const int* __restrict__ row,
                       const int* __restrict__ deg,
                       const int* __restrict__ perm,
                       const float* __restrict__ invd,
                       float* __restrict__ agg) {
    int node = blockIdx.x * 8 + (threadIdx.x >> 5);
    int lane = threadIdx.x & 31;
    if (node >= N_NODES) return;
    int beg = row[node];
    int end = beg + deg[node];

    float4 acc = make_float4(0.f, 0.f, 0.f, 0.f);
    for (int j = beg; j < end; j += 32) {
        int nj = min(32, end - j);
        int s = (j + lane < end) ? __ldg(&perm[j + lane]) : 0;
        int k = 0;
        for (; k + 8 <= nj; k += 8) {
            int s0 = __shfl_sync(0xffffffffu, s, k);
            int s1 = __shfl_sync(0xffffffffu, s, k + 1);
            int s2 = __shfl_sync(0xffffffffu, s, k + 2);
            int s3 = __shfl_sync(0xffffffffu, s, k + 3);
            int s4 = __shfl_sync(0xffffffffu, s, k + 4);
            int s5 = __shfl_sync(0xffffffffu, s, k + 5);
            int s6 = __shfl_sync(0xffffffffu, s, k + 6);
            int s7 = __shfl_sync(0xffffffffu, s, k + 7);
            float4 v0 = ((const float4*)h)[s0 * D4 + lane];
            float4 v1 = ((const float4*)h)[s1 * D4 + lane];
            float4 v2 = ((const float4*)h)[s2 * D4 + lane];
            float4 v3 = ((const float4*)h)[s3 * D4 + lane];
            float4 v4 = ((const float4*)h)[s4 * D4 + lane];
            float4 v5 = ((const float4*)h)[s5 * D4 + lane];
            float4 v6 = ((const float4*)h)[s6 * D4 + lane];
            float4 v7 = ((const float4*)h)[s7 * D4 + lane];
            acc.x += (v0.x + v1.x) + (v2.x + v3.x) + (v4.x + v5.x) + (v6.x + v7.x);
            acc.y += (v0.y + v1.y) + (v2.y + v3.y) + (v4.y + v5.y) + (v6.y + v7.y);
            acc.z += (v0.z + v1.z) + (v2.z + v3.z) + (v4.z + v5.z) + (v6.z + v7.z);
            acc.w += (v0.w + v1.w) + (v2.w + v3.w) + (v4.w + v5.w) + (v6.w + v7.w);
        }
        for (; k < nj; k++) {
            int sk = __shfl_sync(0xffffffffu, s, k);
            float4 v = ((const float4*)h)[sk * D4 + lane];
            acc.x += v.x; acc.y += v.y; acc.z += v.z; acc.w += v.w;
        }
    }
    float iv = invd[node];
    acc.x *= iv; acc.y *= iv; acc.z *= iv; acc.w *= iv;
    ((float4*)agg)[node * D4 + lane] = acc;
}

// ---------------- tensor-core combine (warp mma.sync, bf16 hi/lo) ----------
__device__ __forceinline__ void mma_bf16(float c[4], uint32_t a0, uint32_t a1,
                                         uint32_t a2, uint32_t a3,
                                         uint32_t b0, uint32_t b1) {
    asm volatile(
        "mma.sync.aligned.m16n8k16.row.col.f32.bf16.bf16.f32 "
        "{%0,%1,%2,%3}, {%4,%5,%6,%7}, {%8,%9}, {%0,%1,%2,%3};"
        : "+f"(c[0]), "+f"(c[1]), "+f"(c[2]), "+f"(c[3])
        : "r"(a0), "r"(a1), "r"(a2), "r"(a3), "r"(b0), "r"(b1));
}

// out[n][c] = act( agg[n].Wl[c] + bl[c] + h[n].Wr[c] )
// Block: 128 nodes x 128 cols, 256 threads (8 warps, each 32x64 tile).
__global__ __launch_bounds__(256)
void mma_combine_kernel(const float* __restrict__ agg,
                        const float* __restrict__ h,
                        const __nv_bfloat16* __restrict__ WhiL,
                        const __nv_bfloat16* __restrict__ WloL,
                        const __nv_bfloat16* __restrict__ WhiR,
                        const __nv_bfloat16* __restrict__ WloR,
                        const float* __restrict__ bl,
                        float* __restrict__ out,
                        int relu) {
    extern __shared__ __align__(16) char smem[];
    __nv_bfloat16* sWhi = (__nv_bfloat16*)smem;                    // [128][SWS]
    __nv_bfloat16* sWlo = sWhi + D * SWS;
    __nv_bfloat16* sAhi = sWlo + D * SWS;                          // [128][SWS]
    __nv_bfloat16* sAlo = sAhi + MT * SWS;
    float* sbias = (float*)(sAlo + MT * SWS);                      // [128]

    int tid = threadIdx.x;
    int wid = tid >> 5, lane = tid & 31;
    int g = lane >> 2, tig = lane & 3;
    int n0 = blockIdx.x * MT;
    int r0 = (wid & 3) * 32;          // warp row base within tile (0..96)
    int cb = (wid >> 2) * 64;         // warp col base (0 or 64)

    if (tid < 128) sbias[tid] = bl[tid];

    float C[2][8][4];
    #pragma unroll
    for (int m = 0; m < 2; m++)
        #pragma unroll
        for (int nt = 0; nt < 8; nt++)
            #pragma unroll
            for (int q = 0; q < 4; q++) C[m][nt][q] = 0.f;

    for (int pass = 0; pass < 2; pass++) {
        const float* asrc = pass ? h : agg;
        const __nv_bfloat16* whi = pass ? WhiR : WhiL;
        const __nv_bfloat16* wlo = pass ? WloR : WloL;
        __syncthreads();   // previous pass's smem fully consumed

        for (int i = tid; i < D * 16; i += 256) {
            int r = i >> 4, c16 = i & 15;
            *(uint4*)&sWhi[r * SWS + c16 * 8] = ((const uint4*)whi)[r * 16 + c16];
            *(uint4*)&sWlo[r * SWS + c16 * 8] = ((const uint4*)wlo)[r * 16 + c16];
        }
        for (int i = tid; i < MT * 32; i += 256) {
            int r = i >> 5, c4 = i & 31;
            int node = n0 + r;
            float4 v = make_float4(0.f, 0.f, 0.f, 0.f);
            if (node < N_NODES) v = ((const float4*)asrc)[node * 32 + c4];
            __nv_bfloat162 h01 = __floats2bfloat162_rn(v.x, v.y);
            __nv_bfloat162 h23 = __floats2bfloat162_rn(v.z, v.w);
            float2 f01 = __bfloat1622float2(h01);
            float2 f23 = __bfloat1622float2(h23);
            __nv_bfloat162 l01 = __floats2bfloat162_rn(v.x - f01.x, v.y - f01.y);
            __nv_bfloat162 l23 = __floats2bfloat162_rn(v.z - f23.x, v.w - f23.y);
            uint2 uh, ul;
            uh.x = *(unsigned*)&h01; uh.y = *(unsigned*)&h23;
            ul.x = *(unsigned*)&l01; ul.y = *(unsigned*)&l23;
            *(uint2*)&sAhi[r * SWS + c4 * 4] = uh;
            *(uint2*)&sAlo[r * SWS + c4 * 4] = ul;
        }
        __syncthreads();

        #pragma unroll
        for (int ks = 0; ks < 8; ks++) {
            int kc = ks * 16 + tig * 2;
            uint32_t ah[2][4], al[2][4];
            #pragma unroll
            for (int m = 0; m < 2; m++) {
                int arow = r0 + m * 16 + g;
                ah[m][0] = *(uint32_t*)&sAhi[arow * SWS + kc];
                ah[m][1] = *(uint32_t*)&sAhi[(arow + 8) * SWS + kc];
                ah[m][2] = *(uint32_t*)&sAhi[arow * SWS + kc + 8];
                ah[m][3] = *(uint32_t*)&sAhi[(arow + 8) * SWS + kc + 8];
                al[m][0] = *(uint32_t*)&sAlo[arow * SWS + kc];
                al[m][1] = *(uint32_t*)&sAlo[(arow + 8) * SWS + kc];
                al[m][2] = *(uint32_t*)&sAlo[arow * SWS + kc + 8];
                al[m][3] = *(uint32_t*)&sAlo[(arow + 8) * SWS + kc + 8];
            }
            #pragma unroll
            for (int nt = 0; nt < 8; nt++) {
                int nrow = cb + nt * 8 + g;
                uint32_t bh0 = *(uint32_t*)&sWhi[nrow * SWS + kc];
                uint32_t bh1 = *(uint32_t*)&sWhi[nrow * SWS + kc + 8];
                uint32_t bl0 = *(uint32_t*)&sWlo[nrow * SWS + kc];
                uint32_t bl1 = *(uint32_t*)&sWlo[nrow * SWS + kc + 8];
                #pragma unroll
                for (int m = 0; m < 2; m++) {
                    mma_bf16(C[m][nt], ah[m][0], ah[m][1], ah[m][2], ah[m][3], bh0, bh1);
                    mma_bf16(C[m][nt], ah[m][0], ah[m][1], ah[m][2], ah[m][3], bl0, bl1);
                    mma_bf16(C[m][nt], al[m][0], al[m][1], al[m][2], al[m][3], bh0, bh1);
                }
            }
        }
    }

    #pragma unroll
    for (int m = 0; m < 2; m++) {
        int row0 = n0 + r0 + m * 16 + g;
        int row1 = row0 + 8;
        #pragma unroll
        for (int nt = 0; nt < 8; nt++) {
            int col = cb + nt * 8 + tig * 2;
            float b0 = sbias[col], b1 = sbias[col + 1];
            float2 o0, o1;
            o0.x = C[m][nt][0] + b0; o0.y = C[m][nt][1] + b1;
            o1.x = C[m][nt][2] + b0; o1.y = C[m][nt][3] + b1;
            if (relu) {
                o0.x = fmaxf(o0.x, 0.f); o0.y = fmaxf(o0.y, 0.f);
                o1.x = fmaxf(o1.x, 0.f); o1.y = fmaxf(o1.y, 0.f);
            }
            if (row0 < N_NODES) *(float2*)&out[row0 * D + col] = o0;
            if (row1 < N_NODES) *(float2*)&out[row1 * D + col] = o1;
        }
    }
}

// ---------------- launch ----------------

extern "C" void kernel_launch(void* const* d_in, const int* in_sizes, int n_in,
                              void* d_out, int out_size) {
    const int*   x    = (const int*)d_in[0];
    const int*   ei   = (const int*)d_in[1];
    const float* syn  = (const float*)d_in[2];
    const float* lem  = (const float*)d_in[3];
    const float* pos  = (const float*)d_in[4];
    const float* sen  = (const float*)d_in[5];
    const float* ln_g = (const float*)d_in[6];
    const float* ln_b = (const float*)d_in[7];
    const float* Wl0  = (const float*)d_in[8];
    const float* bl0  = (const float*)d_in[9];
    const float* Wr0  = (const float*)d_in[10];
    const float* Wl1  = (const float*)d_in[11];
    const float* bl1  = (const float*)d_in[12];
    const float* Wr1  = (const float*)d_in[13];
    float* out = (float*)d_out;

    float *h0, *h1, *agg, *invd;
    __nv_bfloat16 *whi, *wlo;
    int *deg, *row, *cursor, *perm;
    cudaGetSymbolAddress((void**)&h0,     g_h0);
    cudaGetSymbolAddress((void**)&h1,     g_h1);
    cudaGetSymbolAddress((void**)&agg,    g_agg);
    cudaGetSymbolAddress((void**)&whi,    g_Whi);
    cudaGetSymbolAddress((void**)&wlo,    g_Wlo);
    cudaGetSymbolAddress((void**)&deg,    g_deg);
    cudaGetSymbolAddress((void**)&row,    g_row);
    cudaGetSymbolAddress((void**)&cursor, g_cursor);
    cudaGetSymbolAddress((void**)&invd,   g_invd);
    cudaGetSymbolAddress((void**)&perm,   g_perm);

    const int smem_bytes = 4 * D * SWS * 2 + D * 4;
    cudaFuncSetAttribute(mma_combine_kernel,
                         cudaFuncAttributeMaxDynamicSharedMemorySize, smem_bytes);

    const int eblocks = (N_EDGES + 255) / 256;
    const int gather_blocks = (N_NODES + 7) / 8;
    const int mma_blocks = (N_NODES + MT - 1) / MT;   // 391

    // single memset: deg[0..N_NODES-1] + total cursor at deg[N_NODES]
    cudaMemsetAsync(deg, 0, (N_NODES + 1) * sizeof(int));

    // 1. embeddings + LayerNorm + edge-degree count (fused)
    embed_count_kernel<<<N_NODES, 128>>>(x, syn, lem, pos, sen, ln_g, ln_b,
                                         ei, deg, h0);

    // 2. CSR segment allocation + weight hi/lo split (fused; grid exactly 256x256)
    alloc_wsplit_kernel<<<256, 256>>>(deg, row, cursor, invd,
                                      Wl0, Wr0, Wl1, Wr1, whi, wlo);

    // 3. permutation fill
    build_perm_kernel<<<eblocks, 256>>>(ei, cursor, perm);

    // 4. layer 0 gather (profile slot #4)
    gather_agg_kernel<<<gather_blocks, 256>>>(h0, row, deg, perm, invd, agg);

    // 5. layer 0 combine
    mma_combine_kernel<<<mma_blocks, 256, smem_bytes>>>(agg, h0,
        whi + 0 * D * D, wlo + 0 * D * D, whi + 1 * D * D, wlo + 1 * D * D,
        bl0, h1, 1);

    // 6-7. layer 1
    gather_agg_kernel<<<gather_blocks, 256>>>(h1, row, deg, perm, invd, agg);
    mma_combine_kernel<<<mma_blocks, 256, smem_bytes>>>(agg, h1,
        whi + 2 * D * D, wlo + 2 * D * D, whi + 3 * D * D, wlo + 3 * D * D,
        bl1, out, 0);
}

// round 16
// speedup vs baseline: 1.4207x; 1.0318x over previous
#include <cuda_runtime.h>
#include <cuda_bf16.h>
#include <math.h>
#include <stdint.h>

#define N_NODES 50000
#define N_EDGES 800000
#define D 128
#define D4 (D / 4)
#define LN_EPS 1e-12f

#define MT 128                // nodes per MMA block
#define SWS 136               // smem row stride in bf16 (conflict-free)

// ---------------- scratch (no allocation allowed) ----------------
__device__ __align__(16) float g_h0[N_NODES * D];
__device__ __align__(16) float g_h1[N_NODES * D];
__device__ __align__(16) float g_agg[N_NODES * D];
__device__ __align__(16) __nv_bfloat16 g_Whi[4][D * D];  // Wl0,Wr0,Wl1,Wr1 hi
__device__ __align__(16) __nv_bfloat16 g_Wlo[4][D * D];  // lo residuals
__device__ int   g_deg[N_NODES + 1];   // [N_NODES] = total cursor
__device__ int   g_row[N_NODES];
__device__ int   g_cursor[N_NODES];
__device__ float g_invd[N_NODES];
__device__ int   g_perm[N_EDGES];

// ---------------- kernels ----------------

// Fused: embeddings + LayerNorm (one block per node) AND in-degree count.
__global__ void embed_count_kernel(const int* __restrict__ x,
                                   const float* __restrict__ syn,
                                   const float* __restrict__ lem,
                                   const float* __restrict__ pos,
                                   const float* __restrict__ sen,
                                   const float* __restrict__ g,
                                   const float* __restrict__ b,
                                   const int* __restrict__ ei,
                                   int* __restrict__ deg,
                                   float* __restrict__ out) {
    int node = blockIdx.x;
    int t = threadIdx.x;

    int gtid = node * 128 + t;
    if (gtid < N_EDGES) atomicAdd(&deg[ei[N_EDGES + gtid]], 1);

    int4 xi = ((const int4*)x)[node];
    float f = syn[(long)xi.x * D + t] + pos[(long)xi.y * D + t] +
              sen[(long)xi.z * D + t] + lem[(long)xi.w * D + t];

    __shared__ float red1[4];
    __shared__ float red2[4];
    int w = t >> 5, l = t & 31;

    float s = f;
    #pragma unroll
    for (int o = 16; o > 0; o >>= 1) s += __shfl_xor_sync(0xffffffffu, s, o);
    if (l == 0) red1[w] = s;
    __syncthreads();
    float mu = (red1[0] + red1[1] + red1[2] + red1[3]) * (1.0f / D);

    float d = f - mu;
    float v = d * d;
    #pragma unroll
    for (int o = 16; o > 0; o >>= 1) v += __shfl_xor_sync(0xffffffffu, v, o);
    if (l == 0) red2[w] = v;
    __syncthreads();
    float var = (red2[0] + red2[1] + red2[2] + red2[3]) * (1.0f / D);

    out[node * D + t] = d * rsqrtf(var + LN_EPS) * g[t] + b[t];
}

// Fused: CSR segment allocation + weight hi/lo split. Grid must be 256x256.
__global__ __launch_bounds__(256)
void alloc_wsplit_kernel(int* __restrict__ deg,
                         int* __restrict__ row,
                         int* __restrict__ cursor,
                         float* __restrict__ invd,
                         const float* __restrict__ w0,
                         const float* __restrict__ w1,
                         const float* __restrict__ w2,
                         const float* __restrict__ w3,
                         __nv_bfloat16* __restrict__ whi,
                         __nv_bfloat16* __restrict__ wlo) {
    int i = blockIdx.x * 256 + threadIdx.x;   // 0 .. 65535 = 4*D*D

    int m = i >> 14;
    const float* w = (m == 0) ? w0 : (m == 1) ? w1 : (m == 2) ? w2 : w3;
    float f = w[i & 16383];
    __nv_bfloat16 hi = __float2bfloat16(f);
    __nv_bfloat16 lo = __float2bfloat16(f - __bfloat162float(hi));
    whi[i] = hi;
    wlo[i] = lo;

    if (i < N_NODES) {
        int d = deg[i];
        int start = atomicAdd(&deg[N_NODES], d);
        row[i] = start;
        cursor[i] = start;
        invd[i] = 1.0f / fmaxf((float)d, 1.0f);
    }
}

// Fill permutation (scalar).
__global__ void build_perm_kernel(const int* __restrict__ ei,
                                  int* __restrict__ cursor,
                                  int* __restrict__ perm) {
    int e = blockIdx.x * blockDim.x + threadIdx.x;
    if (e >= N_EDGES) return;
    int dst = ei[N_EDGES + e];
    int pos = atomicAdd(&cursor[dst], 1);
    perm[pos] = ei[e];
}

// Mean-aggregate via CSR gather. One warp per node; lane = float4 chunk.
// __launch_bounds__(256,6): cap regs -> 48 warps/SM (75% occ).
// perm loads are software-pipelined one 32-batch ahead.
__global__ __launch_bounds__(256, 6)
void gather_agg_kernel(const float* __restrict__ h,
                       const int* __restrict__ row,
                       const int* __restrict__ deg,
                       const int* __restrict__ perm,
                       const float* __restrict__ invd,
                       float* __restrict__ agg) {
    int node = blockIdx.x * 8 + (threadIdx.x >> 5);
    int lane = threadIdx.x & 31;
    if (node >= N_NODES) return;
    int beg = row[node];
    int end = beg + deg[node];

    float4 acc = make_float4(0.f, 0.f, 0.f, 0.f);

    // prefetch first perm batch
    int s = (beg + lane < end) ? __ldg(&perm[beg + lane]) : 0;

    for (int j = beg; j < end; j += 32) {
        int nj = min(32, end - j);
        int s_cur = s;
        // prefetch next batch before consuming this one
        int jn = j + 32;
        if (jn < end)
            s = (jn + lane < end) ? __ldg(&perm[jn + lane]) : 0;

        int k = 0;
        for (; k + 8 <= nj; k += 8) {
            int s0 = __shfl_sync(0xffffffffu, s_cur, k);
            int s1 = __shfl_sync(0xffffffffu, s_cur, k + 1);
            int s2 = __shfl_sync(0xffffffffu, s_cur, k + 2);
            int s3 = __shfl_sync(0xffffffffu, s_cur, k + 3);
            int s4 = __shfl_sync(0xffffffffu, s_cur, k + 4);
            int s5 = __shfl_sync(0xffffffffu, s_cur, k + 5);
            int s6 = __shfl_sync(0xffffffffu, s_cur, k + 6);
            int s7 = __shfl_sync(0xffffffffu, s_cur, k + 7);
            float4 v0 = ((const float4*)h)[s0 * D4 + lane];
            float4 v1 = ((const float4*)h)[s1 * D4 + lane];
            float4 v2 = ((const float4*)h)[s2 * D4 + lane];
            float4 v3 = ((const float4*)h)[s3 * D4 + lane];
            float4 v4 = ((const float4*)h)[s4 * D4 + lane];
            float4 v5 = ((const float4*)h)[s5 * D4 + lane];
            float4 v6 = ((const float4*)h)[s6 * D4 + lane];
            float4 v7 = ((const float4*)h)[s7 * D4 + lane];
            acc.x += (v0.x + v1.x) + (v2.x + v3.x) + (v4.x + v5.x) + (v6.x + v7.x);
            acc.y += (v0.y + v1.y) + (v2.y + v3.y) + (v4.y + v5.y) + (v6.y + v7.y);
            acc.z += (v0.z + v1.z) + (v2.z + v3.z) + (v4.z + v5.z) + (v6.z + v7.z);
            acc.w += (v0.w + v1.w) + (v2.w + v3.w) + (v4.w + v5.w) + (v6.w + v7.w);
        }
        for (; k < nj; k++) {
            int sk = __shfl_sync(0xffffffffu, s_cur, k);
            float4 v = ((const float4*)h)[sk * D4 + lane];
            acc.x += v.x; acc.y += v.y; acc.z += v.z; acc.w += v.w;
        }
    }
    float iv = invd[node];
    acc.x *= iv; acc.y *= iv; acc.z *= iv; acc.w *= iv;
    ((float4*)agg)[node * D4 + lane] = acc;
}

// ---------------- tensor-core combine (warp mma.sync, bf16 hi/lo) ----------
__device__ __forceinline__ void mma_bf16(float c[4], uint32_t a0, uint32_t a1,
                                         uint32_t a2, uint32_t a3,
                                         uint32_t b0, uint32_t b1) {
    asm volatile(
        "mma.sync.aligned.m16n8k16.row.col.f32.bf16.bf16.f32 "
        "{%0,%1,%2,%3}, {%4,%5,%6,%7}, {%8,%9}, {%0,%1,%2,%3};"
        : "+f"(c[0]), "+f"(c[1]), "+f"(c[2]), "+f"(c[3])
        : "r"(a0), "r"(a1), "r"(a2), "r"(a3), "r"(b0), "r"(b1));
}

// out[n][c] = act( agg[n].Wl[c] + bl[c] + h[n].Wr[c] )
// Block: 128 nodes x 128 cols, 256 threads (8 warps, each 32x64 tile).
__global__ __launch_bounds__(256)
void mma_combine_kernel(const float* __restrict__ agg,
                        const float* __restrict__ h,
                        const __nv_bfloat16* __restrict__ WhiL,
                        const __nv_bfloat16* __restrict__ WloL,
                        const __nv_bfloat16* __restrict__ WhiR,
                        const __nv_bfloat16* __restrict__ WloR,
                        const float* __restrict__ bl,
                        float* __restrict__ out,
                        int relu) {
    extern __shared__ __align__(16) char smem[];
    __nv_bfloat16* sWhi = (__nv_bfloat16*)smem;                    // [128][SWS]
    __nv_bfloat16* sWlo = sWhi + D * SWS;
    __nv_bfloat16* sAhi = sWlo + D * SWS;                          // [128][SWS]
    __nv_bfloat16* sAlo = sAhi + MT * SWS;
    float* sbias = (float*)(sAlo + MT * SWS);                      // [128]

    int tid = threadIdx.x;
    int wid = tid >> 5, lane = tid & 31;
    int g = lane >> 2, tig = lane & 3;
    int n0 = blockIdx.x * MT;
    int r0 = (wid & 3) * 32;          // warp row base within tile (0..96)
    int cb = (wid >> 2) * 64;         // warp col base (0 or 64)

    if (tid < 128) sbias[tid] = bl[tid];

    float C[2][8][4];
    #pragma unroll
    for (int m = 0; m < 2; m++)
        #pragma unroll
        for (int nt = 0; nt < 8; nt++)
            #pragma unroll
            for (int q = 0; q < 4; q++) C[m][nt][q] = 0.f;

    for (int pass = 0; pass < 2; pass++) {
        const float* asrc = pass ? h : agg;
        const __nv_bfloat16* whi = pass ? WhiR : WhiL;
        const __nv_bfloat16* wlo = pass ? WloR : WloL;
        __syncthreads();   // previous pass's smem fully consumed

        for (int i = tid; i < D * 16; i += 256) {
            int r = i >> 4, c16 = i & 15;
            *(uint4*)&sWhi[r * SWS + c16 * 8] = ((const uint4*)whi)[r * 16 + c16];
            *(uint4*)&sWlo[r * SWS + c16 * 8] = ((const uint4*)wlo)[r * 16 + c16];
        }
        for (int i = tid; i < MT * 32; i += 256) {
            int r = i >> 5, c4 = i & 31;
            int node = n0 + r;
            float4 v = make_float4(0.f, 0.f, 0.f, 0.f);
            if (node < N_NODES) v = ((const float4*)asrc)[node * 32 + c4];
            __nv_bfloat162 h01 = __floats2bfloat162_rn(v.x, v.y);
            __nv_bfloat162 h23 = __floats2bfloat162_rn(v.z, v.w);
            float2 f01 = __bfloat1622float2(h01);
            float2 f23 = __bfloat1622float2(h23);
            __nv_bfloat162 l01 = __floats2bfloat162_rn(v.x - f01.x, v.y - f01.y);
            __nv_bfloat162 l23 = __floats2bfloat162_rn(v.z - f23.x, v.w - f23.y);
            uint2 uh, ul;
            uh.x = *(unsigned*)&h01; uh.y = *(unsigned*)&h23;
            ul.x = *(unsigned*)&l01; ul.y = *(unsigned*)&l23;
            *(uint2*)&sAhi[r * SWS + c4 * 4] = uh;
            *(uint2*)&sAlo[r * SWS + c4 * 4] = ul;
        }
        __syncthreads();

        #pragma unroll
        for (int ks = 0; ks < 8; ks++) {
            int kc = ks * 16 + tig * 2;
            uint32_t ah[2][4], al[2][4];
            #pragma unroll
            for (int m = 0; m < 2; m++) {
                int arow = r0 + m * 16 + g;
                ah[m][0] = *(uint32_t*)&sAhi[arow * SWS + kc];
                ah[m][1] = *(uint32_t*)&sAhi[(arow + 8) * SWS + kc];
                ah[m][2] = *(uint32_t*)&sAhi[arow * SWS + kc + 8];
                ah[m][3] = *(uint32_t*)&sAhi[(arow + 8) * SWS + kc + 8];
                al[m][0] = *(uint32_t*)&sAlo[arow * SWS + kc];
                al[m][1] = *(uint32_t*)&sAlo[(arow + 8) * SWS + kc];
                al[m][2] = *(uint32_t*)&sAlo[arow * SWS + kc + 8];
                al[m][3] = *(uint32_t*)&sAlo[(arow + 8) * SWS + kc + 8];
            }
            #pragma unroll
            for (int nt = 0; nt < 8; nt++) {
                int nrow = cb + nt * 8 + g;
                uint32_t bh0 = *(uint32_t*)&sWhi[nrow * SWS + kc];
                uint32_t bh1 = *(uint32_t*)&sWhi[nrow * SWS + kc + 8];
                uint32_t bl0 = *(uint32_t*)&sWlo[nrow * SWS + kc];
                uint32_t bl1 = *(uint32_t*)&sWlo[nrow * SWS + kc + 8];
                #pragma unroll
                for (int m = 0; m < 2; m++) {
                    mma_bf16(C[m][nt], ah[m][0], ah[m][1], ah[m][2], ah[m][3], bh0, bh1);
                    mma_bf16(C[m][nt], ah[m][0], ah[m][1], ah[m][2], ah[m][3], bl0, bl1);
                    mma_bf16(C[m][nt], al[m][0], al[m][1], al[m][2], al[m][3], bh0, bh1);
                }
            }
        }
    }

    #pragma unroll
    for (int m = 0; m < 2; m++) {
        int row0 = n0 + r0 + m * 16 + g;
        int row1 = row0 + 8;
        #pragma unroll
        for (int nt = 0; nt < 8; nt++) {
            int col = cb + nt * 8 + tig * 2;
            float b0 = sbias[col], b1 = sbias[col + 1];
            float2 o0, o1;
            o0.x = C[m][nt][0] + b0; o0.y = C[m][nt][1] + b1;
            o1.x = C[m][nt][2] + b0; o1.y = C[m][nt][3] + b1;
            if (relu) {
                o0.x = fmaxf(o0.x, 0.f); o0.y = fmaxf(o0.y, 0.f);
                o1.x = fmaxf(o1.x, 0.f); o1.y = fmaxf(o1.y, 0.f);
            }
            if (row0 < N_NODES) *(float2*)&out[row0 * D + col] = o0;
            if (row1 < N_NODES) *(float2*)&out[row1 * D + col] = o1;
        }
    }
}

// ---------------- launch ----------------

extern "C" void kernel_launch(void* const* d_in, const int* in_sizes, int n_in,
                              void* d_out, int out_size) {
    const int*   x    = (const int*)d_in[0];
    const int*   ei   = (const int*)d_in[1];
    const float* syn  = (const float*)d_in[2];
    const float* lem  = (const float*)d_in[3];
    const float* pos  = (const float*)d_in[4];
    const float* sen  = (const float*)d_in[5];
    const float* ln_g = (const float*)d_in[6];
    const float* ln_b = (const float*)d_in[7];
    const float* Wl0  = (const float*)d_in[8];
    const float* bl0  = (const float*)d_in[9];
    const float* Wr0  = (const float*)d_in[10];
    const float* Wl1  = (const float*)d_in[11];
    const float* bl1  = (const float*)d_in[12];
    const float* Wr1  = (const float*)d_in[13];
    float* out = (float*)d_out;

    float *h0, *h1, *agg, *invd;
    __nv_bfloat16 *whi, *wlo;
    int *deg, *row, *cursor, *perm;
    cudaGetSymbolAddress((void**)&h0,     g_h0);
    cudaGetSymbolAddress((void**)&h1,     g_h1);
    cudaGetSymbolAddress((void**)&agg,    g_agg);
    cudaGetSymbolAddress((void**)&whi,    g_Whi);
    cudaGetSymbolAddress((void**)&wlo,    g_Wlo);
    cudaGetSymbolAddress((void**)&deg,    g_deg);
    cudaGetSymbolAddress((void**)&row,    g_row);
    cudaGetSymbolAddress((void**)&cursor, g_cursor);
    cudaGetSymbolAddress((void**)&invd,   g_invd);
    cudaGetSymbolAddress((void**)&perm,   g_perm);

    const int smem_bytes = 4 * D * SWS * 2 + D * 4;
    cudaFuncSetAttribute(mma_combine_kernel,
                         cudaFuncAttributeMaxDynamicSharedMemorySize, smem_bytes);

    const int eblocks = (N_EDGES + 255) / 256;
    const int gather_blocks = (N_NODES + 7) / 8;
    const int mma_blocks = (N_NODES + MT - 1) / MT;   // 391

    cudaMemsetAsync(deg, 0, (N_NODES + 1) * sizeof(int));

    // 1. embeddings + LayerNorm + edge-degree count (fused)
    embed_count_kernel<<<N_NODES, 128>>>(x, syn, lem, pos, sen, ln_g, ln_b,
                                         ei, deg, h0);

    // 2. CSR segment allocation + weight hi/lo split (fused)
    alloc_wsplit_kernel<<<256, 256>>>(deg, row, cursor, invd,
                                      Wl0, Wr0, Wl1, Wr1, whi, wlo);

    // 3. permutation fill
    build_perm_kernel<<<eblocks, 256>>>(ei, cursor, perm);

    // 4. layer 0 gather (profile slot #4)
    gather_agg_kernel<<<gather_blocks, 256>>>(h0, row, deg, perm, invd, agg);

    // 5. layer 0 combine
    mma_combine_kernel<<<mma_blocks, 256, smem_bytes>>>(agg, h0,
        whi + 0 * D * D, wlo + 0 * D * D, whi + 1 * D * D, wlo + 1 * D * D,
        bl0, h1, 1);

    // 6-7. layer 1
    gather_agg_kernel<<<gather_blocks, 256>>>(h1, row, deg, perm, invd, agg);
    mma_combine_kernel<<<mma_blocks, 256, smem_bytes>>>(agg, h1,
        whi + 2 * D * D, wlo + 2 * D * D, whi + 3 * D * D, wlo + 3 * D * D,
        bl1, out, 0);
}